// round 13
// baseline (speedup 1.0000x reference)
#include <cuda_runtime.h>
#include <cuda_bf16.h>
#include <math.h>
#include <cstdint>

#define BB 8
#define SS 1024
#define DD 1024
#define HH 16
#define HDD 64
#define CDD 512
#define LN_EPS 1e-5f

typedef unsigned short ushort_t;
typedef unsigned int u32;

// ---------------- scratch (device globals; no allocations) ----------------
__device__ float    g_tc[4][DD];
__device__ float    g_v32[BB * SS * DD];            // 32 MB
__device__ float    g_x[BB * SS * DD];              // 32 MB
__device__ ushort_t g_hi[4][BB * SS * DD];          // 64 MB
__device__ ushort_t g_lo[4][BB * SS * DD];          // 64 MB (lo used for V and x)
__device__ ushort_t g_whi[DD * DD];                 // 2 MB
__device__ ushort_t g_wlo[DD * DD];                 // 2 MB
__device__ ushort_t g_qkvh[3][BB * SS * DD];        // 48 MB
__device__ float    g_vsum[BB * HH * HDD];          // 32 KB
__device__ ushort_t g_e[(size_t)BB * HH * SS * SS]; // 268 MB (exp(E/8) bf16; L2-transient)

// ---------------- helpers ----------------
__device__ __forceinline__ void mma_bf16(float4& d, const u32 a[4], u32 b0, u32 b1) {
    asm volatile("mma.sync.aligned.m16n8k16.row.col.f32.bf16.bf16.f32 "
                 "{%0,%1,%2,%3}, {%4,%5,%6,%7}, {%8,%9}, {%0,%1,%2,%3};"
                 : "+f"(d.x), "+f"(d.y), "+f"(d.z), "+f"(d.w)
                 : "r"(a[0]), "r"(a[1]), "r"(a[2]), "r"(a[3]), "r"(b0), "r"(b1));
}
__device__ __forceinline__ void stcs2(float* p, float a, float b) {
    asm volatile("st.global.cs.v2.f32 [%0], {%1,%2};" :: "l"(p), "f"(a), "f"(b));
}
__device__ __forceinline__ u32 pack_bf16x2(float a, float b) {
    return (u32)__bfloat16_as_ushort(__float2bfloat16(a))
         | ((u32)__bfloat16_as_ushort(__float2bfloat16(b)) << 16);
}
__device__ __forceinline__ float bf_lo(u32 w) {
    return __bfloat162float(__ushort_as_bfloat16((ushort_t)(w & 0xffffu)));
}
__device__ __forceinline__ float bf_hi(u32 w) {
    return __bfloat162float(__ushort_as_bfloat16((ushort_t)(w >> 16)));
}
__device__ __forceinline__ void cp16(ushort_t* s, const ushort_t* g) {
    u32 sa = (u32)__cvta_generic_to_shared(s);
    asm volatile("cp.async.cg.shared.global [%0], [%1], 16;" :: "r"(sa), "l"(g));
}
#define CP_COMMIT() asm volatile("cp.async.commit_group;" ::: "memory")
#define CP_WAIT(n)  asm volatile("cp.async.wait_group %0;" :: "n"(n) : "memory")

// ---------------- kernel 1: tc_p = LayerNorm(code @ wc_w^T + wc_b) ----------------
struct TcParams {
    const float* code;
    const float* wcw[4];
    const float* wcb[4];
    const float* lng[4];
    const float* lnb[4];
};

__global__ __launch_bounds__(256) void tc_kernel(TcParams P) {
    int p = blockIdx.x, t = threadIdx.x;
    __shared__ float sc[CDD];
    __shared__ float raw[DD];
    __shared__ float red[256];
    for (int i = t; i < CDD; i += 256) sc[i] = P.code[i];
    __syncthreads();
    const float* w  = P.wcw[p];
    const float* wb = P.wcb[p];
    for (int k = 0; k < 4; k++) {
        int d = t + k * 256;
        const float4* wr = (const float4*)(w + (size_t)d * CDD);
        const float4* s4 = (const float4*)sc;
        float s = wb[d];
        #pragma unroll 8
        for (int c = 0; c < CDD / 4; c++) {
            float4 wv = wr[c];
            float4 cv = s4[c];
            s += wv.x * cv.x + wv.y * cv.y + wv.z * cv.z + wv.w * cv.w;
        }
        raw[d] = s;
    }
    __syncthreads();
    float ls = 0.f, lq = 0.f;
    for (int k = 0; k < 4; k++) {
        float v = raw[t + k * 256];
        ls += v; lq += v * v;
    }
    red[t] = ls; __syncthreads();
    for (int o = 128; o > 0; o >>= 1) { if (t < o) red[t] += red[t + o]; __syncthreads(); }
    float sum = red[0]; __syncthreads();
    red[t] = lq; __syncthreads();
    for (int o = 128; o > 0; o >>= 1) { if (t < o) red[t] += red[t + o]; __syncthreads(); }
    float sq  = red[0];
    float mu  = sum * (1.f / DD);
    float var = sq * (1.f / DD) - mu * mu;
    float inv = rsqrtf(var + LN_EPS);
    const float* g  = P.lng[p];
    const float* be = P.lnb[p];
    for (int k = 0; k < 4; k++) {
        int d = t + k * 256;
        g_tc[p][d] = (raw[d] - mu) * inv * g[d] + be[d];
    }
}

// ---------------- conversions ----------------
__device__ __forceinline__ void split_store(float4 a, ushort_t* hi, ushort_t* lo,
                                            size_t i4, int want_lo) {
    unsigned hx = __bfloat16_as_ushort(__float2bfloat16(a.x));
    unsigned hy = __bfloat16_as_ushort(__float2bfloat16(a.y));
    unsigned hz = __bfloat16_as_ushort(__float2bfloat16(a.z));
    unsigned hw = __bfloat16_as_ushort(__float2bfloat16(a.w));
    ((uint2*)hi)[i4] = make_uint2(hx | (hy << 16), hz | (hw << 16));
    if (want_lo) {
        float rx = a.x - __bfloat162float(__ushort_as_bfloat16((ushort_t)hx));
        float ry = a.y - __bfloat162float(__ushort_as_bfloat16((ushort_t)hy));
        float rz = a.z - __bfloat162float(__ushort_as_bfloat16((ushort_t)hz));
        float rw = a.w - __bfloat162float(__ushort_as_bfloat16((ushort_t)hw));
        unsigned lx = __bfloat16_as_ushort(__float2bfloat16(rx));
        unsigned ly = __bfloat16_as_ushort(__float2bfloat16(ry));
        unsigned lz = __bfloat16_as_ushort(__float2bfloat16(rz));
        unsigned lw = __bfloat16_as_ushort(__float2bfloat16(rw));
        ((uint2*)lo)[i4] = make_uint2(lx | (ly << 16), lz | (lw << 16));
    }
}

__global__ __launch_bounds__(256) void conv_in_kernel(const float* __restrict__ q,
                                                      const float* __restrict__ k,
                                                      const float* __restrict__ v) {
    int z = blockIdx.y;
    const float* in = (z == 0) ? q : (z == 1) ? k : v;
    size_t i4 = (size_t)blockIdx.x * 256 + threadIdx.x;
    float4 a = ((const float4*)in)[i4];
    int kc = (int)((i4 * 4) & (DD - 1));
    float4 t = *(const float4*)&g_tc[z][kc];
    a.x *= t.x; a.y *= t.y; a.z *= t.z; a.w *= t.w;
    split_store(a, g_hi[z], g_lo[z], i4, z == 2);
}

__global__ __launch_bounds__(256) void conv_x_kernel() {
    size_t i4 = (size_t)blockIdx.x * 256 + threadIdx.x;
    float4 a = ((const float4*)g_x)[i4];
    int kc = (int)((i4 * 4) & (DD - 1));
    float4 t = *(const float4*)&g_tc[3][kc];
    a.x *= t.x; a.y *= t.y; a.z *= t.z; a.w *= t.w;
    split_store(a, g_hi[3], g_lo[3], i4, 1);
}

__global__ __launch_bounds__(256) void conv_w_kernel(const float* __restrict__ W) {
    size_t i4 = (size_t)blockIdx.x * 256 + threadIdx.x;
    float4 a = ((const float4*)W)[i4];
    split_store(a, g_whi, g_wlo, i4, 1);
}

// ---------------- vsum ----------------
__global__ __launch_bounds__(512) void vsum_kernel() {
    int bh = blockIdx.x;
    int b = bh >> 4, h = bh & 15;
    int tid = threadIdx.x;
    int d = tid & 63, jg = tid >> 6;
    const float* Vp = g_v32 + (size_t)b * SS * DD + h * HDD + d;
    float s = 0.f;
    for (int j = jg * 128; j < jg * 128 + 128; j++) s += Vp[(size_t)j * DD];
    __shared__ float rs[512];
    rs[tid] = s;
    __syncthreads();
    if (tid < 64) {
        float t = 0.f;
        #pragma unroll
        for (int k = 0; k < 8; k++) t += rs[k * 64 + tid];
        g_vsum[bh * 64 + tid] = t;
    }
}

// ---------------- projection GEMM on HMMA, single-barrier 2-stage pipeline ---------
// terms derived from z: Q,K 1-term; V and O-proj 3-term.
#define PST 40
#define GST (128 * PST)
#define GEMM_SMEM (4 * 2 * GST * 2 + 512)

__global__ __launch_bounds__(256, 2) void gemm_mma_kernel(const float* __restrict__ bias,
                                                          float* __restrict__ cout, int zbase) {
    extern __shared__ __align__(16) ushort_t gsm[];
    ushort_t* Ah = gsm;
    ushort_t* Al = Ah + 2 * GST;
    ushort_t* Bh = Al + 2 * GST;
    ushort_t* Bl = Bh + 2 * GST;
    float* sbias = (float*)(Bl + 2 * GST);

    int z = blockIdx.z + zbase;
    int terms = (z >= 2) ? 3 : 1;
    const ushort_t* Ahg = g_hi[z];
    const ushort_t* Alg = g_lo[z];
    float*    Cf = (z == 2) ? g_v32 : ((z == 3) ? cout : nullptr);
    ushort_t* Cb = (z < 3) ? g_qkvh[z] : nullptr;

    int tid = threadIdx.x;
    int wid = tid >> 5, lane = tid & 31;
    int g = lane >> 2, tig = lane & 3;
    int wr = wid & 1, wc = wid >> 1;
    int bm = blockIdx.y * 128, bn = blockIdx.x * 128;

    int r0l = tid >> 2, c8l = (tid & 3) * 8;
    int r1l = r0l + 64;

    float4 acc[4][4];
    #pragma unroll
    for (int i = 0; i < 4; i++)
        #pragma unroll
        for (int j = 0; j < 4; j++) acc[i][j] = make_float4(0.f, 0.f, 0.f, 0.f);

    if (tid < 128) sbias[tid] = bias[bn + tid];

    // prologue: chunk 0 -> stage 0
    {
        size_t gA0 = (size_t)(bm + r0l) * DD + c8l, gA1 = (size_t)(bm + r1l) * DD + c8l;
        size_t gB0 = (size_t)(bn + r0l) * DD + c8l, gB1 = (size_t)(bn + r1l) * DD + c8l;
        cp16(&Ah[r0l * PST + c8l], &Ahg[gA0]); cp16(&Ah[r1l * PST + c8l], &Ahg[gA1]);
        cp16(&Bh[r0l * PST + c8l], &g_whi[gB0]); cp16(&Bh[r1l * PST + c8l], &g_whi[gB1]);
        if (terms == 3) {
            cp16(&Al[r0l * PST + c8l], &Alg[gA0]); cp16(&Al[r1l * PST + c8l], &Alg[gA1]);
            cp16(&Bl[r0l * PST + c8l], &g_wlo[gB0]); cp16(&Bl[r1l * PST + c8l], &g_wlo[gB1]);
        }
        CP_COMMIT();
    }

    // single barrier per chunk: wait(own) -> barrier -> issue next -> compute
    #pragma unroll 1
    for (int kc = 0; kc < DD / 32; kc++) {
        CP_WAIT(0);
        __syncthreads();
        if (kc + 1 < DD / 32) {
            int st = ((kc + 1) & 1) * GST;
            int ko = (kc + 1) * 32;
            size_t gA0 = (size_t)(bm + r0l) * DD + ko + c8l, gA1 = (size_t)(bm + r1l) * DD + ko + c8l;
            size_t gB0 = (size_t)(bn + r0l) * DD + ko + c8l, gB1 = (size_t)(bn + r1l) * DD + ko + c8l;
            cp16(&Ah[st + r0l * PST + c8l], &Ahg[gA0]); cp16(&Ah[st + r1l * PST + c8l], &Ahg[gA1]);
            cp16(&Bh[st + r0l * PST + c8l], &g_whi[gB0]); cp16(&Bh[st + r1l * PST + c8l], &g_whi[gB1]);
            if (terms == 3) {
                cp16(&Al[st + r0l * PST + c8l], &Alg[gA0]); cp16(&Al[st + r1l * PST + c8l], &Alg[gA1]);
                cp16(&Bl[st + r0l * PST + c8l], &g_wlo[gB0]); cp16(&Bl[st + r1l * PST + c8l], &g_wlo[gB1]);
            }
            CP_COMMIT();
        }

        int cur = (kc & 1) * GST;
        const ushort_t* Ahc = Ah + cur;
        const ushort_t* Alc = Al + cur;
        const ushort_t* Bhc = Bh + cur;
        const ushort_t* Blc = Bl + cur;
        #pragma unroll
        for (int ks = 0; ks < 2; ks++) {
            int k0 = ks * 16;
            u32 ah[4][4], al[4][4];
            #pragma unroll
            for (int mf = 0; mf < 4; mf++) {
                int r0 = wr * 64 + mf * 16 + g;
                const ushort_t* p0 = Ahc + r0 * PST + k0 + 2 * tig;
                const ushort_t* p1 = p0 + 8 * PST;
                ah[mf][0] = *(const u32*)p0;       ah[mf][1] = *(const u32*)p1;
                ah[mf][2] = *(const u32*)(p0 + 8); ah[mf][3] = *(const u32*)(p1 + 8);
            }
            if (terms == 3) {
                #pragma unroll
                for (int mf = 0; mf < 4; mf++) {
                    int r0 = wr * 64 + mf * 16 + g;
                    const ushort_t* q0 = Alc + r0 * PST + k0 + 2 * tig;
                    const ushort_t* q1 = q0 + 8 * PST;
                    al[mf][0] = *(const u32*)q0;       al[mf][1] = *(const u32*)q1;
                    al[mf][2] = *(const u32*)(q0 + 8); al[mf][3] = *(const u32*)(q1 + 8);
                }
            }
            #pragma unroll
            for (int nf = 0; nf < 4; nf++) {
                int n0 = wc * 32 + nf * 8 + g;
                const ushort_t* bp = Bhc + n0 * PST + k0 + 2 * tig;
                u32 bh0 = *(const u32*)bp, bh1 = *(const u32*)(bp + 8);
                #pragma unroll
                for (int mf = 0; mf < 4; mf++) mma_bf16(acc[mf][nf], ah[mf], bh0, bh1);
                if (terms == 3) {
                    const ushort_t* lp = Blc + n0 * PST + k0 + 2 * tig;
                    u32 bl0 = *(const u32*)lp, bl1 = *(const u32*)(lp + 8);
                    #pragma unroll
                    for (int mf = 0; mf < 4; mf++) mma_bf16(acc[mf][nf], ah[mf], bl0, bl1);
                    #pragma unroll
                    for (int mf = 0; mf < 4; mf++) mma_bf16(acc[mf][nf], al[mf], bh0, bh1);
                }
            }
        }
    }

    #pragma unroll
    for (int mf = 0; mf < 4; mf++) {
        int r0 = bm + wr * 64 + mf * 16 + g;
        #pragma unroll
        for (int nf = 0; nf < 4; nf++) {
            int cl = wc * 32 + nf * 8 + 2 * tig;
            int c  = bn + cl;
            float2 b2 = *(const float2*)&sbias[cl];
            float4 v = acc[mf][nf];
            float o0x = v.x + b2.x, o0y = v.y + b2.y;
            float o1x = v.z + b2.x, o1y = v.w + b2.y;
            if (Cf) {
                *(float2*)&Cf[(size_t)r0 * DD + c]       = make_float2(o0x, o0y);
                *(float2*)&Cf[(size_t)(r0 + 8) * DD + c] = make_float2(o1x, o1y);
            }
            if (Cb) {
                *(u32*)&Cb[(size_t)r0 * DD + c]       = pack_bf16x2(o0x, o0y);
                *(u32*)&Cb[(size_t)(r0 + 8) * DD + c] = pack_bf16x2(o1x, o1y);
            }
        }
    }
}

// ---------------- fused attention: phase A (QK->e, rowsums) + phase B (f, GV) ------
// e slice (64 rows x 1024, bf16, 128 KB/CTA) round-trips through L2 (plain stores,
// .cg readback; working set ~38 MB < L2). .cs only on the 512 MB att output.
#define QS2 72
#define KS2 72
#define ES2 136
#define VS2 132
#define GS2 132
#define F_E 0
#define F_V (F_E + 2 * 64 * ES2)
#define F_G (F_V + 2 * 64 * VS2)
#define F_USH (F_G + 64 * GS2)                       // 42752 ushorts = 85504 B
#define AT_SMEM_BYTES (F_USH * 2 + (SS + 64 + 128) * 4)   // 90368 B -> 2 CTAs/SM

__global__ __launch_bounds__(256, 2) void attn_fused_kernel(const float* __restrict__ u,
                                                            float* __restrict__ att) {
    extern __shared__ __align__(16) char smemc[];
    ushort_t* UA  = (ushort_t*)smemc;
    float* usj  = (float*)(smemc + F_USH * 2);
    float* crow = usj + SS;
    float* red  = crow + 64;

    int tid = threadIdx.x;
    int wid = tid >> 5, lane = tid & 31;
    int g = lane >> 2, tig = lane & 3;
    int wr = wid & 3, wc = wid >> 2;
    int i0 = blockIdx.x * 64;
    int h  = blockIdx.y;
    int b  = blockIdx.z;
    const ushort_t* Qg = g_qkvh[0] + (size_t)b * SS * DD + h * HDD;
    const ushort_t* Kg = g_qkvh[1] + (size_t)b * SS * DD + h * HDD;
    const ushort_t* Vg = g_qkvh[2] + (size_t)b * SS * DD + h * HDD;
    ushort_t* eg = g_e + ((size_t)(b * HH + h) * SS + i0) * SS;

    // ===== phase A: E = QK^T, e = exp(E/8) -> g_e, rowsums -> crow =====
    {
        ushort_t* Qs = UA;                 // [64][QS2]
        ushort_t* Ks = UA + 64 * QS2;      // [2][128][KS2]

        #pragma unroll
        for (int t = 0; t < 2; t++) {
            int i = tid + t * 256;
            int row = i >> 3, c8 = (i & 7) * 8;
            *(uint4*)&Qs[row * QS2 + c8] = *(const uint4*)&Qg[(size_t)(i0 + row) * DD + c8];
        }
        for (int i = tid; i < SS; i += 256) usj[i] = u[b * SS + i];

        // prologue: K chunk 0 -> stage 0
        #pragma unroll
        for (int t = 0; t < 4; t++) {
            int i = tid + t * 256;
            int row = i >> 3, c8 = (i & 7) * 8;
            cp16(&Ks[row * KS2 + c8], &Kg[(size_t)row * DD + c8]);
        }
        CP_COMMIT();

        float s0 = 0.f, s1 = 0.f;
        #pragma unroll 1
        for (int jt = 0; jt < 8; jt++) {
            int j0 = jt * 128;
            CP_WAIT(0);
            __syncthreads();
            if (jt + 1 < 8) {
                int st = ((jt + 1) & 1) * 128 * KS2;
                int j0n = (jt + 1) * 128;
                #pragma unroll
                for (int t = 0; t < 4; t++) {
                    int i = tid + t * 256;
                    int row = i >> 3, c8 = (i & 7) * 8;
                    cp16(&Ks[st + row * KS2 + c8], &Kg[(size_t)(j0n + row) * DD + c8]);
                }
                CP_COMMIT();
            }
            const ushort_t* Kb = Ks + (jt & 1) * 128 * KS2;
            float4 eacc[8];
            #pragma unroll
            for (int nf = 0; nf < 8; nf++) eacc[nf] = make_float4(0.f, 0.f, 0.f, 0.f);
            #pragma unroll
            for (int ks = 0; ks < 4; ks++) {
                int k0 = ks * 16;
                u32 a[4];
                const ushort_t* p0 = Qs + (16 * wr + g) * QS2 + k0 + 2 * tig;
                const ushort_t* p1 = p0 + 8 * QS2;
                a[0] = *(const u32*)p0;       a[1] = *(const u32*)p1;
                a[2] = *(const u32*)(p0 + 8); a[3] = *(const u32*)(p1 + 8);
                #pragma unroll
                for (int nf = 0; nf < 8; nf++) {
                    const ushort_t* q0 = Kb + (64 * wc + nf * 8 + g) * KS2 + k0 + 2 * tig;
                    mma_bf16(eacc[nf], a, *(const u32*)q0, *(const u32*)(q0 + 8));
                }
            }
            int ra = 16 * wr + g, rb = ra + 8;
            ushort_t* ea = eg + (size_t)ra * SS + j0;
            ushort_t* eb = eg + (size_t)rb * SS + j0;
            #pragma unroll
            for (int nf = 0; nf < 8; nf++) {
                int col = 64 * wc + 8 * nf + 2 * tig;
                float4 e = eacc[nf];
                float x0 = __expf(e.x * 0.125f);
                float x1 = __expf(e.y * 0.125f);
                float x2 = __expf(e.z * 0.125f);
                float x3 = __expf(e.w * 0.125f);
                s0 += x0 + x1;
                s1 += x2 + x3;
                *(u32*)&ea[col] = pack_bf16x2(x0, x1);   // plain store: stays in L2
                *(u32*)&eb[col] = pack_bf16x2(x2, x3);
            }
        }
        s0 += __shfl_xor_sync(0xffffffffu, s0, 1);
        s0 += __shfl_xor_sync(0xffffffffu, s0, 2);
        s1 += __shfl_xor_sync(0xffffffffu, s1, 1);
        s1 += __shfl_xor_sync(0xffffffffu, s1, 2);
        if (tig == 0) {
            red[wc * 64 + 16 * wr + g]     = s0;
            red[wc * 64 + 16 * wr + g + 8] = s1;
        }
        __syncthreads();
        if (tid < 64)
            crow[tid] = 1e-6f * (red[tid] + red[64 + tid]) / usj[i0 + tid];
        __syncthreads();   // crow visible; phase-A smem free; e stores CTA-visible
    }

    // ===== phase B: f = t/(c+t) -> att (.cs), G = 1-f, x = colsum(V) - G@V =====
    {
        ushort_t* Es  = UA + F_E;
        ushort_t* Vsh = UA + F_V;
        ushort_t* Gs  = UA + F_G;

        u32 vreg[16];
        #pragma unroll
        for (int t = 0; t < 4; t++) {
            int i = tid + t * 256;
            int row = i >> 4, c8 = (i & 15) * 8;
            cp16(&Es[row * ES2 + c8], &eg[(size_t)row * SS + c8]);
        }
        CP_COMMIT();
        #pragma unroll
        for (int t = 0; t < 16; t++) {
            int i = tid + t * 256;
            int dp = i & 31, j = i >> 5;
            vreg[t] = *(const u32*)&Vg[(size_t)j * DD + 2 * dp];
        }

        int wr2 = wid & 3, wc2 = wid >> 2;
        float4 xacc[4];
        #pragma unroll
        for (int nf = 0; nf < 4; nf++) xacc[nf] = make_float4(0.f, 0.f, 0.f, 0.f);

        #pragma unroll 1
        for (int jt = 0; jt < 8; jt++) {
            int j0 = jt * 128;
            if (jt + 1 < 8) {
                int st = ((jt + 1) & 1) * 64 * ES2;
                int j0n = (jt + 1) * 128;
                #pragma unroll
                for (int t = 0; t < 4; t++) {
                    int i = tid + t * 256;
                    int row = i >> 4, c8 = (i & 15) * 8;
                    cp16(&Es[st + row * ES2 + c8], &eg[(size_t)row * SS + j0n + c8]);
                }
                CP_COMMIT();
            }
            {
                ushort_t* Vb = Vsh + (jt & 1) * 64 * VS2;
                #pragma unroll
                for (int t = 0; t < 16; t++) {
                    int i = tid + t * 256;
                    int dp = i & 31, j = i >> 5;
                    u32 vh = vreg[t];
                    Vb[(2 * dp) * VS2 + j]     = (ushort_t)(vh & 0xffffu);
                    Vb[(2 * dp + 1) * VS2 + j] = (ushort_t)(vh >> 16);
                }
            }
            if (jt + 1 < 8) {
                int j0n = (jt + 1) * 128;
                #pragma unroll
                for (int t = 0; t < 16; t++) {
                    int i = tid + t * 256;
                    int dp = i & 31, j = i >> 5;
                    vreg[t] = *(const u32*)&Vg[(size_t)(j0n + j) * DD + 2 * dp];
                }
            }
            if (jt + 1 < 8) { CP_WAIT(1); } else { CP_WAIT(0); }
            __syncthreads();

            const ushort_t* Eb = Es + (jt & 1) * 64 * ES2;
            const ushort_t* Vb = Vsh + (jt & 1) * 64 * VS2;

            int ra = 16 * wr + g, rb = ra + 8;
            float ca = crow[ra], cb = crow[rb];
            float* atta = att + (((size_t)(b * HH + h)) * SS + (i0 + ra)) * SS + j0;
            float* attb = att + (((size_t)(b * HH + h)) * SS + (i0 + rb)) * SS + j0;
            #pragma unroll
            for (int nf = 0; nf < 8; nf++) {
                int col = 64 * wc + 8 * nf + 2 * tig;
                u32 wa  = *(const u32*)&Eb[ra * ES2 + col];
                u32 wb2 = *(const u32*)&Eb[rb * ES2 + col];
                float2 uj = *(const float2*)&usj[j0 + col];
                float t0 = uj.x * bf_lo(wa);
                float t1 = uj.y * bf_hi(wa);
                float t2 = uj.x * bf_lo(wb2);
                float t3 = uj.y * bf_hi(wb2);
                float f0 = __fdividef(t0, ca + t0);
                float f1 = __fdividef(t1, ca + t1);
                float f2 = __fdividef(t2, cb + t2);
                float f3 = __fdividef(t3, cb + t3);
                stcs2(atta + col, f0, f1);
                stcs2(attb + col, f2, f3);
                *(u32*)&Gs[ra * GS2 + col] = pack_bf16x2(1.f - f0, 1.f - f1);
                *(u32*)&Gs[rb * GS2 + col] = pack_bf16x2(1.f - f2, 1.f - f3);
            }
            __syncthreads();
            #pragma unroll
            for (int ks = 0; ks < 8; ks++) {
                int k0 = ks * 16;
                u32 a[4];
                const ushort_t* p0 = Gs + (16 * wr2 + g) * GS2 + k0 + 2 * tig;
                const ushort_t* p1 = p0 + 8 * GS2;
                a[0] = *(const u32*)p0;       a[1] = *(const u32*)p1;
                a[2] = *(const u32*)(p0 + 8); a[3] = *(const u32*)(p1 + 8);
                #pragma unroll
                for (int nf = 0; nf < 4; nf++) {
                    const ushort_t* q0 = Vb + (32 * wc2 + nf * 8 + g) * VS2 + k0 + 2 * tig;
                    mma_bf16(xacc[nf], a, *(const u32*)q0, *(const u32*)(q0 + 8));
                }
            }
            __syncthreads();
        }

        // epilogue: x = colsum(V) - G@V
        const float* vs = g_vsum + (b * HH + h) * HDD;
        int ra = 16 * wr2 + g, rb = ra + 8;
        #pragma unroll
        for (int nf = 0; nf < 4; nf++) {
            int col = 32 * wc2 + 8 * nf + 2 * tig;
            float2 v2 = *(const float2*)&vs[col];
            float4 xv = xacc[nf];
            float* xa = g_x + ((size_t)b * SS + i0 + ra) * DD + h * HDD + col;
            float* xb = g_x + ((size_t)b * SS + i0 + rb) * DD + h * HDD + col;
            *(float2*)xa = make_float2(v2.x - xv.x, v2.y - xv.y);
            *(float2*)xb = make_float2(v2.x - xv.z, v2.y - xv.w);
        }
    }
}

// ---------------- launch ----------------
extern "C" void kernel_launch(void* const* d_in, const int* in_sizes, int n_in,
                              void* d_out, int out_size) {
    const float* query = (const float*)d_in[0];
    const float* key   = (const float*)d_in[1];
    const float* value = (const float*)d_in[2];
    const float* u     = (const float*)d_in[3];
    const float* code  = (const float*)d_in[4];
    const float* W     = (const float*)d_in[5];
    const float* bias  = (const float*)d_in[6];

    TcParams tp;
    tp.code = code;
    for (int p = 0; p < 4; p++) {
        tp.wcw[p] = (const float*)d_in[7 + 4 * p];
        tp.wcb[p] = (const float*)d_in[8 + 4 * p];
        tp.lng[p] = (const float*)d_in[9 + 4 * p];
        tp.lnb[p] = (const float*)d_in[10 + 4 * p];
    }

    cudaFuncSetAttribute(gemm_mma_kernel, cudaFuncAttributeMaxDynamicSharedMemorySize,
                         GEMM_SMEM);
    cudaFuncSetAttribute(attn_fused_kernel, cudaFuncAttributeMaxDynamicSharedMemorySize,
                         AT_SMEM_BYTES);

    // 1) transformed codes
    tc_kernel<<<4, 256>>>(tp);
    // 2) split-bf16 conversions (tc folded in; lo only for V)
    conv_in_kernel<<<dim3(BB * SS * DD / 4 / 256, 3), 256>>>(query, key, value);
    conv_w_kernel<<<DD * DD / 4 / 256, 256>>>(W);
    // 3) Q/K/V projections in ONE launch (terms per z: Q,K 1-term; V 3-term)
    gemm_mma_kernel<<<dim3(DD / 128, BB * SS / 128, 3), 256, GEMM_SMEM>>>(bias, nullptr, 0);
    // 4) colsum of V
    vsum_kernel<<<BB * HH, 512>>>();
    // 5) fused attention -> att region of d_out (.cs) + g_x
    float* att = (float*)d_out + (size_t)BB * SS * DD;
    attn_fused_kernel<<<dim3(SS / 64, HH, BB), 256, AT_SMEM_BYTES>>>(u, att);
    // 6) split-convert x, then O-projection (3-term) -> x region of d_out
    conv_x_kernel<<<BB * SS * DD / 4 / 256, 256>>>();
    gemm_mma_kernel<<<dim3(DD / 128, BB * SS / 128, 1), 256, GEMM_SMEM>>>(bias, (float*)d_out, 3);
}

// round 15
// speedup vs baseline: 1.1619x; 1.1619x over previous
#include <cuda_runtime.h>
#include <cuda_bf16.h>
#include <math.h>
#include <cstdint>

#define BB 8
#define SS 1024
#define DD 1024
#define HH 16
#define HDD 64
#define CDD 512
#define LN_EPS 1e-5f

typedef unsigned short ushort_t;
typedef unsigned int u32;

// ---------------- scratch (device globals; no allocations) ----------------
__device__ float    g_tc[4][DD];
__device__ float    g_v32[BB * SS * DD];            // 32 MB
__device__ float    g_x[BB * SS * DD];              // 32 MB
__device__ ushort_t g_hi[4][BB * SS * DD];          // 64 MB
__device__ ushort_t g_lo[4][BB * SS * DD];          // 64 MB (lo used for V and x)
__device__ ushort_t g_whi[DD * DD];                 // 2 MB
__device__ ushort_t g_wlo[DD * DD];                 // 2 MB
__device__ ushort_t g_qkvh[3][BB * SS * DD];        // 48 MB
__device__ float    g_vsum[BB * HH * HDD];          // 32 KB
__device__ ushort_t g_e[(size_t)BB * HH * SS * SS]; // 268 MB (exp(E/8) bf16; L2-transient)

// ---------------- helpers ----------------
__device__ __forceinline__ void mma_bf16(float4& d, const u32 a[4], u32 b0, u32 b1) {
    asm volatile("mma.sync.aligned.m16n8k16.row.col.f32.bf16.bf16.f32 "
                 "{%0,%1,%2,%3}, {%4,%5,%6,%7}, {%8,%9}, {%0,%1,%2,%3};"
                 : "+f"(d.x), "+f"(d.y), "+f"(d.z), "+f"(d.w)
                 : "r"(a[0]), "r"(a[1]), "r"(a[2]), "r"(a[3]), "r"(b0), "r"(b1));
}
__device__ __forceinline__ void ldsm4(u32 r[4], u32 addr) {
    asm volatile("ldmatrix.sync.aligned.m8n8.x4.shared.b16 {%0,%1,%2,%3}, [%4];"
                 : "=r"(r[0]), "=r"(r[1]), "=r"(r[2]), "=r"(r[3]) : "r"(addr));
}
__device__ __forceinline__ void ldsm4t(u32 r[4], u32 addr) {
    asm volatile("ldmatrix.sync.aligned.m8n8.x4.trans.shared.b16 {%0,%1,%2,%3}, [%4];"
                 : "=r"(r[0]), "=r"(r[1]), "=r"(r[2]), "=r"(r[3]) : "r"(addr));
}
__device__ __forceinline__ void stcs2(float* p, float a, float b) {
    asm volatile("st.global.cs.v2.f32 [%0], {%1,%2};" :: "l"(p), "f"(a), "f"(b));
}
__device__ __forceinline__ u32 pack_bf16x2(float a, float b) {
    return (u32)__bfloat16_as_ushort(__float2bfloat16(a))
         | ((u32)__bfloat16_as_ushort(__float2bfloat16(b)) << 16);
}
__device__ __forceinline__ float bf_lo(u32 w) {
    return __bfloat162float(__ushort_as_bfloat16((ushort_t)(w & 0xffffu)));
}
__device__ __forceinline__ float bf_hi(u32 w) {
    return __bfloat162float(__ushort_as_bfloat16((ushort_t)(w >> 16)));
}
__device__ __forceinline__ void cp16(ushort_t* s, const ushort_t* g) {
    u32 sa = (u32)__cvta_generic_to_shared(s);
    asm volatile("cp.async.cg.shared.global [%0], [%1], 16;" :: "r"(sa), "l"(g));
}
__device__ __forceinline__ u32 smem_u32p(const void* p) {
    return (u32)__cvta_generic_to_shared(p);
}
#define CP_COMMIT() asm volatile("cp.async.commit_group;" ::: "memory")
#define CP_WAIT(n)  asm volatile("cp.async.wait_group %0;" :: "n"(n) : "memory")

// ---------------- kernel 1: tc_p = LayerNorm(code @ wc_w^T + wc_b) ----------------
struct TcParams {
    const float* code;
    const float* wcw[4];
    const float* wcb[4];
    const float* lng[4];
    const float* lnb[4];
};

__global__ __launch_bounds__(256) void tc_kernel(TcParams P) {
    int p = blockIdx.x, t = threadIdx.x;
    __shared__ float sc[CDD];
    __shared__ float raw[DD];
    __shared__ float red[256];
    for (int i = t; i < CDD; i += 256) sc[i] = P.code[i];
    __syncthreads();
    const float* w  = P.wcw[p];
    const float* wb = P.wcb[p];
    for (int k = 0; k < 4; k++) {
        int d = t + k * 256;
        const float4* wr = (const float4*)(w + (size_t)d * CDD);
        const float4* s4 = (const float4*)sc;
        float s = wb[d];
        #pragma unroll 8
        for (int c = 0; c < CDD / 4; c++) {
            float4 wv = wr[c];
            float4 cv = s4[c];
            s += wv.x * cv.x + wv.y * cv.y + wv.z * cv.z + wv.w * cv.w;
        }
        raw[d] = s;
    }
    __syncthreads();
    float ls = 0.f, lq = 0.f;
    for (int k = 0; k < 4; k++) {
        float v = raw[t + k * 256];
        ls += v; lq += v * v;
    }
    red[t] = ls; __syncthreads();
    for (int o = 128; o > 0; o >>= 1) { if (t < o) red[t] += red[t + o]; __syncthreads(); }
    float sum = red[0]; __syncthreads();
    red[t] = lq; __syncthreads();
    for (int o = 128; o > 0; o >>= 1) { if (t < o) red[t] += red[t + o]; __syncthreads(); }
    float sq  = red[0];
    float mu  = sum * (1.f / DD);
    float var = sq * (1.f / DD) - mu * mu;
    float inv = rsqrtf(var + LN_EPS);
    const float* g  = P.lng[p];
    const float* be = P.lnb[p];
    for (int k = 0; k < 4; k++) {
        int d = t + k * 256;
        g_tc[p][d] = (raw[d] - mu) * inv * g[d] + be[d];
    }
}

// ---------------- conversions ----------------
__device__ __forceinline__ void split_store(float4 a, ushort_t* hi, ushort_t* lo,
                                            size_t i4, int want_lo) {
    unsigned hx = __bfloat16_as_ushort(__float2bfloat16(a.x));
    unsigned hy = __bfloat16_as_ushort(__float2bfloat16(a.y));
    unsigned hz = __bfloat16_as_ushort(__float2bfloat16(a.z));
    unsigned hw = __bfloat16_as_ushort(__float2bfloat16(a.w));
    ((uint2*)hi)[i4] = make_uint2(hx | (hy << 16), hz | (hw << 16));
    if (want_lo) {
        float rx = a.x - __bfloat162float(__ushort_as_bfloat16((ushort_t)hx));
        float ry = a.y - __bfloat162float(__ushort_as_bfloat16((ushort_t)hy));
        float rz = a.z - __bfloat162float(__ushort_as_bfloat16((ushort_t)hz));
        float rw = a.w - __bfloat162float(__ushort_as_bfloat16((ushort_t)hw));
        unsigned lx = __bfloat16_as_ushort(__float2bfloat16(rx));
        unsigned ly = __bfloat16_as_ushort(__float2bfloat16(ry));
        unsigned lz = __bfloat16_as_ushort(__float2bfloat16(rz));
        unsigned lw = __bfloat16_as_ushort(__float2bfloat16(rw));
        ((uint2*)lo)[i4] = make_uint2(lx | (ly << 16), lz | (lw << 16));
    }
}

__global__ __launch_bounds__(256) void conv_in_kernel(const float* __restrict__ q,
                                                      const float* __restrict__ k,
                                                      const float* __restrict__ v) {
    int z = blockIdx.y;
    const float* in = (z == 0) ? q : (z == 1) ? k : v;
    size_t i4 = (size_t)blockIdx.x * 256 + threadIdx.x;
    float4 a = ((const float4*)in)[i4];
    int kc = (int)((i4 * 4) & (DD - 1));
    float4 t = *(const float4*)&g_tc[z][kc];
    a.x *= t.x; a.y *= t.y; a.z *= t.z; a.w *= t.w;
    split_store(a, g_hi[z], g_lo[z], i4, z == 2);
}

__global__ __launch_bounds__(256) void conv_x_kernel() {
    size_t i4 = (size_t)blockIdx.x * 256 + threadIdx.x;
    float4 a = ((const float4*)g_x)[i4];
    int kc = (int)((i4 * 4) & (DD - 1));
    float4 t = *(const float4*)&g_tc[3][kc];
    a.x *= t.x; a.y *= t.y; a.z *= t.z; a.w *= t.w;
    split_store(a, g_hi[3], g_lo[3], i4, 1);
}

__global__ __launch_bounds__(256) void conv_w_kernel(const float* __restrict__ W) {
    size_t i4 = (size_t)blockIdx.x * 256 + threadIdx.x;
    float4 a = ((const float4*)W)[i4];
    split_store(a, g_whi, g_wlo, i4, 1);
}

// ---------------- vsum ----------------
__global__ __launch_bounds__(512) void vsum_kernel() {
    int bh = blockIdx.x;
    int b = bh >> 4, h = bh & 15;
    int tid = threadIdx.x;
    int d = tid & 63, jg = tid >> 6;
    const float* Vp = g_v32 + (size_t)b * SS * DD + h * HDD + d;
    float s = 0.f;
    for (int j = jg * 128; j < jg * 128 + 128; j++) s += Vp[(size_t)j * DD];
    __shared__ float rs[512];
    rs[tid] = s;
    __syncthreads();
    if (tid < 64) {
        float t = 0.f;
        #pragma unroll
        for (int k = 0; k < 8; k++) t += rs[k * 64 + tid];
        g_vsum[bh * 64 + tid] = t;
    }
}

// ---------------- projection GEMM on HMMA, ldmatrix fragments ----------------
// terms derived from z: Q,K 1-term; V and O-proj 3-term.
#define PST 40
#define GST (128 * PST)
#define GEMM_SMEM (4 * 2 * GST * 2 + 512)

__global__ __launch_bounds__(256, 2) void gemm_mma_kernel(const float* __restrict__ bias,
                                                          float* __restrict__ cout, int zbase) {
    extern __shared__ __align__(16) ushort_t gsm[];
    ushort_t* Ah = gsm;
    ushort_t* Al = Ah + 2 * GST;
    ushort_t* Bh = Al + 2 * GST;
    ushort_t* Bl = Bh + 2 * GST;
    float* sbias = (float*)(Bl + 2 * GST);

    int z = blockIdx.z + zbase;
    int terms = (z >= 2) ? 3 : 1;
    const ushort_t* Ahg = g_hi[z];
    const ushort_t* Alg = g_lo[z];
    float*    Cf = (z == 2) ? g_v32 : ((z == 3) ? cout : nullptr);
    ushort_t* Cb = (z < 3) ? g_qkvh[z] : nullptr;

    int tid = threadIdx.x;
    int wid = tid >> 5, lane = tid & 31;
    int g = lane >> 2, tig = lane & 3;
    int wr = wid & 1, wc = wid >> 1;
    int bm = blockIdx.y * 128, bn = blockIdx.x * 128;

    int r0l = tid >> 2, c8l = (tid & 3) * 8;
    int r1l = r0l + 64;

    // ldmatrix per-lane offsets (bytes)
    int aoff = ((lane & 15) * PST + ((lane >> 4) << 3)) * 2;
    int boff = (((lane & 7) + ((lane >> 4) << 3)) * PST + (((lane >> 3) & 1) << 3)) * 2;
    u32 AhU = smem_u32p(Ah) + aoff;
    u32 AlU = smem_u32p(Al) + aoff;
    u32 BhU = smem_u32p(Bh) + boff;
    u32 BlU = smem_u32p(Bl) + boff;

    float4 acc[4][4];
    #pragma unroll
    for (int i = 0; i < 4; i++)
        #pragma unroll
        for (int j = 0; j < 4; j++) acc[i][j] = make_float4(0.f, 0.f, 0.f, 0.f);

    if (tid < 128) sbias[tid] = bias[bn + tid];

    // prologue: chunk 0 -> stage 0
    {
        size_t gA0 = (size_t)(bm + r0l) * DD + c8l, gA1 = (size_t)(bm + r1l) * DD + c8l;
        size_t gB0 = (size_t)(bn + r0l) * DD + c8l, gB1 = (size_t)(bn + r1l) * DD + c8l;
        cp16(&Ah[r0l * PST + c8l], &Ahg[gA0]); cp16(&Ah[r1l * PST + c8l], &Ahg[gA1]);
        cp16(&Bh[r0l * PST + c8l], &g_whi[gB0]); cp16(&Bh[r1l * PST + c8l], &g_whi[gB1]);
        if (terms == 3) {
            cp16(&Al[r0l * PST + c8l], &Alg[gA0]); cp16(&Al[r1l * PST + c8l], &Alg[gA1]);
            cp16(&Bl[r0l * PST + c8l], &g_wlo[gB0]); cp16(&Bl[r1l * PST + c8l], &g_wlo[gB1]);
        }
        CP_COMMIT();
    }

    #pragma unroll 1
    for (int kc = 0; kc < DD / 32; kc++) {
        CP_WAIT(0);
        __syncthreads();
        if (kc + 1 < DD / 32) {
            int st = ((kc + 1) & 1) * GST;
            int ko = (kc + 1) * 32;
            size_t gA0 = (size_t)(bm + r0l) * DD + ko + c8l, gA1 = (size_t)(bm + r1l) * DD + ko + c8l;
            size_t gB0 = (size_t)(bn + r0l) * DD + ko + c8l, gB1 = (size_t)(bn + r1l) * DD + ko + c8l;
            cp16(&Ah[st + r0l * PST + c8l], &Ahg[gA0]); cp16(&Ah[st + r1l * PST + c8l], &Ahg[gA1]);
            cp16(&Bh[st + r0l * PST + c8l], &g_whi[gB0]); cp16(&Bh[st + r1l * PST + c8l], &g_whi[gB1]);
            if (terms == 3) {
                cp16(&Al[st + r0l * PST + c8l], &Alg[gA0]); cp16(&Al[st + r1l * PST + c8l], &Alg[gA1]);
                cp16(&Bl[st + r0l * PST + c8l], &g_wlo[gB0]); cp16(&Bl[st + r1l * PST + c8l], &g_wlo[gB1]);
            }
            CP_COMMIT();
        }

        int stage = (kc & 1) * GST;
        #pragma unroll
        for (int ks = 0; ks < 2; ks++) {
            int base2 = (stage + ks * 16) * 2;   // byte offset of k0 within stage
            u32 ah[4][4], al[4][4], bh4[2][4], bl4[2][4];
            #pragma unroll
            for (int mf = 0; mf < 4; mf++)
                ldsm4(ah[mf], AhU + base2 + ((wr * 64 + mf * 16) * PST) * 2);
            if (terms == 3) {
                #pragma unroll
                for (int mf = 0; mf < 4; mf++)
                    ldsm4(al[mf], AlU + base2 + ((wr * 64 + mf * 16) * PST) * 2);
            }
            #pragma unroll
            for (int np = 0; np < 2; np++) {
                ldsm4(bh4[np], BhU + base2 + ((wc * 32 + np * 16) * PST) * 2);
                if (terms == 3)
                    ldsm4(bl4[np], BlU + base2 + ((wc * 32 + np * 16) * PST) * 2);
            }
            #pragma unroll
            for (int np = 0; np < 2; np++) {
                #pragma unroll
                for (int s = 0; s < 2; s++) {
                    int nf = np * 2 + s;
                    u32 bh0 = bh4[np][2 * s], bh1 = bh4[np][2 * s + 1];
                    #pragma unroll
                    for (int mf = 0; mf < 4; mf++) mma_bf16(acc[mf][nf], ah[mf], bh0, bh1);
                    if (terms == 3) {
                        u32 bl0 = bl4[np][2 * s], bl1 = bl4[np][2 * s + 1];
                        #pragma unroll
                        for (int mf = 0; mf < 4; mf++) mma_bf16(acc[mf][nf], ah[mf], bl0, bl1);
                        #pragma unroll
                        for (int mf = 0; mf < 4; mf++) mma_bf16(acc[mf][nf], al[mf], bh0, bh1);
                    }
                }
            }
        }
    }

    #pragma unroll
    for (int mf = 0; mf < 4; mf++) {
        int r0 = bm + wr * 64 + mf * 16 + g;
        #pragma unroll
        for (int nf = 0; nf < 4; nf++) {
            int cl = wc * 32 + nf * 8 + 2 * tig;
            int c  = bn + cl;
            float2 b2 = *(const float2*)&sbias[cl];
            float4 v = acc[mf][nf];
            float o0x = v.x + b2.x, o0y = v.y + b2.y;
            float o1x = v.z + b2.x, o1y = v.w + b2.y;
            if (Cf) {
                *(float2*)&Cf[(size_t)r0 * DD + c]       = make_float2(o0x, o0y);
                *(float2*)&Cf[(size_t)(r0 + 8) * DD + c] = make_float2(o1x, o1y);
            }
            if (Cb) {
                *(u32*)&Cb[(size_t)r0 * DD + c]       = pack_bf16x2(o0x, o0y);
                *(u32*)&Cb[(size_t)(r0 + 8) * DD + c] = pack_bf16x2(o1x, o1y);
            }
        }
    }
}

// ---------------- fused attention: phase A (QK->e, rowsums) + phase B (f, GV) ------
#define QS2 72
#define KS2 72
#define ES2 136
#define VS  72
#define GS2 136
#define F_E 0
#define F_V (F_E + 2 * 64 * ES2)          // Es: 2 stages [64][ES2]
#define F_G (F_V + 2 * 128 * VS)          // Vsh: 2 stages [128][VS] (natural [j][d])
#define F_USH (F_G + 64 * GS2)            // Gs: [64][GS2]   -> 44544 ushorts
#define AT_SMEM_BYTES (F_USH * 2 + (SS + 64 + 128) * 4)   // 93952 B -> 2 CTAs/SM

__global__ __launch_bounds__(256, 2) void attn_fused_kernel(const float* __restrict__ u,
                                                            float* __restrict__ att) {
    extern __shared__ __align__(16) char smemc[];
    ushort_t* UA  = (ushort_t*)smemc;
    float* usj  = (float*)(smemc + F_USH * 2);
    float* crow = usj + SS;
    float* red  = crow + 64;

    int tid = threadIdx.x;
    int wid = tid >> 5, lane = tid & 31;
    int g = lane >> 2, tig = lane & 3;
    int wr = wid & 3, wc = wid >> 2;
    int i0 = blockIdx.x * 64;
    int h  = blockIdx.y;
    int b  = blockIdx.z;
    const ushort_t* Qg = g_qkvh[0] + (size_t)b * SS * DD + h * HDD;
    const ushort_t* Kg = g_qkvh[1] + (size_t)b * SS * DD + h * HDD;
    const ushort_t* Vg = g_qkvh[2] + (size_t)b * SS * DD + h * HDD;
    ushort_t* eg = g_e + ((size_t)(b * HH + h) * SS + i0) * SS;

    // ===== phase A =====
    {
        ushort_t* Qs = UA;                 // [64][QS2]
        ushort_t* Ks = UA + 64 * QS2;      // [2][128][KS2]
        int qoff = ((lane & 15) * QS2 + ((lane >> 4) << 3)) * 2;
        int kboff = (((lane & 7) + ((lane >> 4) << 3)) * KS2 + (((lane >> 3) & 1) << 3)) * 2;
        u32 QsU = smem_u32p(Qs) + qoff;
        u32 KsU = smem_u32p(Ks) + kboff;

        #pragma unroll
        for (int t = 0; t < 2; t++) {
            int i = tid + t * 256;
            int row = i >> 3, c8 = (i & 7) * 8;
            *(uint4*)&Qs[row * QS2 + c8] = *(const uint4*)&Qg[(size_t)(i0 + row) * DD + c8];
        }
        for (int i = tid; i < SS; i += 256) usj[i] = u[b * SS + i];

        #pragma unroll
        for (int t = 0; t < 4; t++) {
            int i = tid + t * 256;
            int row = i >> 3, c8 = (i & 7) * 8;
            cp16(&Ks[row * KS2 + c8], &Kg[(size_t)row * DD + c8]);
        }
        CP_COMMIT();

        float s0 = 0.f, s1 = 0.f;
        #pragma unroll 1
        for (int jt = 0; jt < 8; jt++) {
            int j0 = jt * 128;
            CP_WAIT(0);
            __syncthreads();
            if (jt + 1 < 8) {
                int st = ((jt + 1) & 1) * 128 * KS2;
                int j0n = (jt + 1) * 128;
                #pragma unroll
                for (int t = 0; t < 4; t++) {
                    int i = tid + t * 256;
                    int row = i >> 3, c8 = (i & 7) * 8;
                    cp16(&Ks[st + row * KS2 + c8], &Kg[(size_t)(j0n + row) * DD + c8]);
                }
                CP_COMMIT();
            }
            int stage2 = ((jt & 1) * 128 * KS2) * 2;
            float4 eacc[8];
            #pragma unroll
            for (int nf = 0; nf < 8; nf++) eacc[nf] = make_float4(0.f, 0.f, 0.f, 0.f);
            #pragma unroll
            for (int ks = 0; ks < 4; ks++) {
                u32 a[4];
                ldsm4(a, QsU + ((16 * wr) * QS2 + ks * 16) * 2);
                #pragma unroll
                for (int np = 0; np < 4; np++) {
                    u32 kb[4];
                    ldsm4(kb, KsU + stage2 + ((64 * wc + np * 16) * KS2 + ks * 16) * 2);
                    mma_bf16(eacc[2 * np],     a, kb[0], kb[1]);
                    mma_bf16(eacc[2 * np + 1], a, kb[2], kb[3]);
                }
            }
            int ra = 16 * wr + g, rb = ra + 8;
            ushort_t* ea = eg + (size_t)ra * SS + j0;
            ushort_t* eb = eg + (size_t)rb * SS + j0;
            #pragma unroll
            for (int nf = 0; nf < 8; nf++) {
                int col = 64 * wc + 8 * nf + 2 * tig;
                float4 e = eacc[nf];
                float x0 = __expf(e.x * 0.125f);
                float x1 = __expf(e.y * 0.125f);
                float x2 = __expf(e.z * 0.125f);
                float x3 = __expf(e.w * 0.125f);
                s0 += x0 + x1;
                s1 += x2 + x3;
                *(u32*)&ea[col] = pack_bf16x2(x0, x1);
                *(u32*)&eb[col] = pack_bf16x2(x2, x3);
            }
        }
        s0 += __shfl_xor_sync(0xffffffffu, s0, 1);
        s0 += __shfl_xor_sync(0xffffffffu, s0, 2);
        s1 += __shfl_xor_sync(0xffffffffu, s1, 1);
        s1 += __shfl_xor_sync(0xffffffffu, s1, 2);
        if (tig == 0) {
            red[wc * 64 + 16 * wr + g]     = s0;
            red[wc * 64 + 16 * wr + g + 8] = s1;
        }
        __syncthreads();
        if (tid < 64)
            crow[tid] = 1e-6f * (red[tid] + red[64 + tid]) / usj[i0 + tid];
        __syncthreads();
    }

    // ===== phase B =====
    {
        ushort_t* Es  = UA + F_E;          // [2][64][ES2]
        ushort_t* Vsh = UA + F_V;          // [2][128][VS]  natural [j][d]
        ushort_t* Gs  = UA + F_G;          // [64][GS2]
        int goff = ((lane & 15) * GS2 + ((lane >> 4) << 3)) * 2;
        int voff = (((lane & 7) + (((lane >> 3) & 1) << 3)) * VS + ((lane >> 4) << 3)) * 2;
        u32 GsU = smem_u32p(Gs) + goff;
        u32 VsU = smem_u32p(Vsh) + voff;

        // prologue: e tile 0 + V tile 0
        #pragma unroll
        for (int t = 0; t < 4; t++) {
            int i = tid + t * 256;
            int row = i >> 4, c8 = (i & 15) * 8;
            cp16(&Es[row * ES2 + c8], &eg[(size_t)row * SS + c8]);
        }
        #pragma unroll
        for (int t = 0; t < 4; t++) {
            int i = tid + t * 256;
            int row = i >> 3, c8 = (i & 7) * 8;
            cp16(&Vsh[row * VS + c8], &Vg[(size_t)row * DD + c8]);
        }
        CP_COMMIT();

        int wr2 = wid & 3, wc2 = wid >> 2;
        float4 xacc[4];
        #pragma unroll
        for (int nf = 0; nf < 4; nf++) xacc[nf] = make_float4(0.f, 0.f, 0.f, 0.f);

        #pragma unroll 1
        for (int jt = 0; jt < 8; jt++) {
            int j0 = jt * 128;
            CP_WAIT(0);
            __syncthreads();
            if (jt + 1 < 8) {
                int stE = ((jt + 1) & 1) * 64 * ES2;
                int stV = ((jt + 1) & 1) * 128 * VS;
                int j0n = (jt + 1) * 128;
                #pragma unroll
                for (int t = 0; t < 4; t++) {
                    int i = tid + t * 256;
                    int row = i >> 4, c8 = (i & 15) * 8;
                    cp16(&Es[stE + row * ES2 + c8], &eg[(size_t)row * SS + j0n + c8]);
                }
                #pragma unroll
                for (int t = 0; t < 4; t++) {
                    int i = tid + t * 256;
                    int row = i >> 3, c8 = (i & 7) * 8;
                    cp16(&Vsh[stV + row * VS + c8], &Vg[(size_t)(j0n + row) * DD + c8]);
                }
                CP_COMMIT();
            }

            const ushort_t* Eb = Es + (jt & 1) * 64 * ES2;
            int vstage2 = ((jt & 1) * 128 * VS) * 2;

            int ra = 16 * wr + g, rb = ra + 8;
            float ca = crow[ra], cb = crow[rb];
            float* atta = att + (((size_t)(b * HH + h)) * SS + (i0 + ra)) * SS + j0;
            float* attb = att + (((size_t)(b * HH + h)) * SS + (i0 + rb)) * SS + j0;
            #pragma unroll
            for (int nf = 0; nf < 8; nf++) {
                int col = 64 * wc + 8 * nf + 2 * tig;
                u32 wa  = *(const u32*)&Eb[ra * ES2 + col];
                u32 wb2 = *(const u32*)&Eb[rb * ES2 + col];
                float2 uj = *(const float2*)&usj[j0 + col];
                float t0 = uj.x * bf_lo(wa);
                float t1 = uj.y * bf_hi(wa);
                float t2 = uj.x * bf_lo(wb2);
                float t3 = uj.y * bf_hi(wb2);
                float f0 = __fdividef(t0, ca + t0);
                float f1 = __fdividef(t1, ca + t1);
                float f2 = __fdividef(t2, cb + t2);
                float f3 = __fdividef(t3, cb + t3);
                stcs2(atta + col, f0, f1);
                stcs2(attb + col, f2, f3);
                *(u32*)&Gs[ra * GS2 + col] = pack_bf16x2(1.f - f0, 1.f - f1);
                *(u32*)&Gs[rb * GS2 + col] = pack_bf16x2(1.f - f2, 1.f - f3);
            }
            __syncthreads();
            #pragma unroll
            for (int ks = 0; ks < 8; ks++) {
                u32 a[4];
                ldsm4(a, GsU + ((16 * wr2) * GS2 + ks * 16) * 2);
                #pragma unroll
                for (int np = 0; np < 2; np++) {
                    u32 vb[4];
                    ldsm4t(vb, VsU + vstage2 + ((ks * 16) * VS + 32 * wc2 + np * 16) * 2);
                    mma_bf16(xacc[2 * np],     a, vb[0], vb[1]);
                    mma_bf16(xacc[2 * np + 1], a, vb[2], vb[3]);
                }
            }
        }

        // epilogue: x = colsum(V) - G@V
        const float* vs = g_vsum + (b * HH + h) * HDD;
        int ra = 16 * wr2 + g, rb = ra + 8;
        #pragma unroll
        for (int nf = 0; nf < 4; nf++) {
            int col = 32 * wc2 + 8 * nf + 2 * tig;
            float2 v2 = *(const float2*)&vs[col];
            float4 xv = xacc[nf];
            float* xa = g_x + ((size_t)b * SS + i0 + ra) * DD + h * HDD + col;
            float* xb = g_x + ((size_t)b * SS + i0 + rb) * DD + h * HDD + col;
            *(float2*)xa = make_float2(v2.x - xv.x, v2.y - xv.y);
            *(float2*)xb = make_float2(v2.x - xv.z, v2.y - xv.w);
        }
    }
}

// ---------------- launch ----------------
extern "C" void kernel_launch(void* const* d_in, const int* in_sizes, int n_in,
                              void* d_out, int out_size) {
    const float* query = (const float*)d_in[0];
    const float* key   = (const float*)d_in[1];
    const float* value = (const float*)d_in[2];
    const float* u     = (const float*)d_in[3];
    const float* code  = (const float*)d_in[4];
    const float* W     = (const float*)d_in[5];
    const float* bias  = (const float*)d_in[6];

    TcParams tp;
    tp.code = code;
    for (int p = 0; p < 4; p++) {
        tp.wcw[p] = (const float*)d_in[7 + 4 * p];
        tp.wcb[p] = (const float*)d_in[8 + 4 * p];
        tp.lng[p] = (const float*)d_in[9 + 4 * p];
        tp.lnb[p] = (const float*)d_in[10 + 4 * p];
    }

    cudaFuncSetAttribute(gemm_mma_kernel, cudaFuncAttributeMaxDynamicSharedMemorySize,
                         GEMM_SMEM);
    cudaFuncSetAttribute(attn_fused_kernel, cudaFuncAttributeMaxDynamicSharedMemorySize,
                         AT_SMEM_BYTES);

    // 1) transformed codes
    tc_kernel<<<4, 256>>>(tp);
    // 2) split-bf16 conversions (tc folded in; lo only for V)
    conv_in_kernel<<<dim3(BB * SS * DD / 4 / 256, 3), 256>>>(query, key, value);
    conv_w_kernel<<<DD * DD / 4 / 256, 256>>>(W);
    // 3) Q/K/V projections in ONE launch (terms per z: Q,K 1-term; V 3-term)
    gemm_mma_kernel<<<dim3(DD / 128, BB * SS / 128, 3), 256, GEMM_SMEM>>>(bias, nullptr, 0);
    // 4) colsum of V
    vsum_kernel<<<BB * HH, 512>>>();
    // 5) fused attention -> att region of d_out (.cs) + g_x
    float* att = (float*)d_out + (size_t)BB * SS * DD;
    attn_fused_kernel<<<dim3(SS / 64, HH, BB), 256, AT_SMEM_BYTES>>>(u, att);
    // 6) split-convert x, then O-projection (3-term) -> x region of d_out
    conv_x_kernel<<<BB * SS * DD / 4 / 256, 256>>>();
    gemm_mma_kernel<<<dim3(DD / 128, BB * SS / 128, 1), 256, GEMM_SMEM>>>(bias, (float*)d_out, 3);
}